// round 6
// baseline (speedup 1.0000x reference)
#include <cuda_runtime.h>
#include <cstdint>
#include <cstddef>

// Problem constants
#define NB   8
#define CB   128
#define NC   1024          // NB*CB
#define HH   160
#define WW   160
#define NA   180
#define NR   180
#define AR   (NA*NR)       // 32400
#define PIX  (HH*WW)       // 25600
#define WR   20            // staged rho-window rows (true span <= 18)
#define PH   12            // angles per staging phase
#define PPI  15            // phases per chunk-iter (NA/PH)
#define ITERS 8            // channel iters per CTA (128 ch / 16)
#define NF   (ITERS*PPI)   // 120 total phases
#define TPB  256

// Scratch in __device__ globals (no allocation allowed)
__device__ float         g_T[(size_t)AR * NC];       // transposed: T[a][r][nc]
__device__ unsigned char g_idx[(size_t)NA * PIX];    // r index table [a][y][x]
__device__ double        g_tab[2 * NA];              // cos/irho, sin/irho

// ---------------------------------------------------------------------------
// Kernel 0: trig table (fp64, once)
// ---------------------------------------------------------------------------
__global__ void tab_kernel()
{
    int a = threadIdx.x;
    if (a < NA) {
        const double PI = 3.14159265358979323846;
        double th = (double)a * (PI / 180.0);
        double irho = 227.0 / 180.0;   // (int(sqrt(160^2+160^2))+1)/180
        g_tab[a]      = cos(th) / irho;
        g_tab[NA + a] = sin(th) / irho;
    }
}

// ---------------------------------------------------------------------------
// Kernel 1: rho-index table (fp64 FMA-class ops only; matches numpy exactly)
// ---------------------------------------------------------------------------
__global__ void build_idx_kernel()
{
    const int a = blockIdx.y;
    double tc = g_tab[a], ts = g_tab[NA + a];
    int p = blockIdx.x * 256 + threadIdx.x;
    int y = p / WW, x = p - y * WW;
    double v = __dadd_rn(__dmul_rn((double)(x - 80), tc),
                         __dmul_rn((double)(y - 80), ts));
    int r = (int)rint(v) + 90;
    r = min(NR - 1, max(0, r));
    g_idx[(size_t)a * PIX + p] = (unsigned char)r;
}

// ---------------------------------------------------------------------------
// Kernel 2: transpose In[NC][AR] -> T[AR][NC]
// ---------------------------------------------------------------------------
__global__ void transpose_kernel(const float* __restrict__ in)
{
    __shared__ float tile[32][33];
    int ar0 = blockIdx.x * 32;
    int nc0 = blockIdx.y * 32;
    int tx = threadIdx.x;
    int ty = threadIdx.y;
    #pragma unroll
    for (int i = ty; i < 32; i += 8) {
        int ar = ar0 + tx;
        if (ar < AR) tile[i][tx] = in[(size_t)(nc0 + i) * AR + ar];
    }
    __syncthreads();
    #pragma unroll
    for (int i = ty; i < 32; i += 8) {
        int ar = ar0 + i;
        if (ar < AR) g_T[(size_t)ar * NC + nc0 + tx] = tile[tx][i];
    }
}

// ---------------------------------------------------------------------------
// Kernel 3: main inverse-Hough.
//   CTA = 16x16 pixel tile x 128 ch, 256 thr.
//   Thread = 2x2 pixel block (b = tid&63) x 4-ch slot (j = tid>>6).
//   Walk 00->10->11->01 per angle with delta-packed idx (r0:5b + 3x3b
//   signed deltas, 2 angles per u32). Reload (predicated, branch-free)
//   only when delta != 0 => ~2.5 LDS.128 per 4 pixels instead of 4.
//   Values staged per phase (12 angles x 20 rows x 16 ch) via cp.async,
//   double-buffered.
// ---------------------------------------------------------------------------
__device__ __forceinline__ void cp16(unsigned smem_addr, const void* gptr)
{
    asm volatile("cp.async.cg.shared.global [%0], [%1], 16;\n"
                 :: "r"(smem_addr), "l"(gptr));
}

__global__ void __launch_bounds__(TPB, 3) iht_main_kernel(float* __restrict__ out)
{
    __shared__ __align__(16) char sbuf[2][PH * 4 * WR * 16];  // 2 x 15360 B
    __shared__ unsigned sidxp[64 * 97];                       // 24832 B
    __shared__ unsigned char sbase[192];

    const int tid = threadIdx.x;
    const int x0 = blockIdx.x * 16;
    const int y0 = blockIdx.y * 16;
    const int cz0 = blockIdx.z * 128;
    const int b  = tid & 63;
    const int j  = tid >> 6;
    const int bx = b & 7, by = b >> 3;
    const int gx = x0 + 2 * bx, gy = y0 + 2 * by;

    // ---- per-angle window base (min over tile corners; affine => corners) ----
    for (int a = tid; a < NA; a += TPB) {
        const unsigned char* s = g_idx + (size_t)a * PIX + y0 * WW + x0;
        int m = min(min((int)s[0], (int)s[15]),
                    min((int)s[15 * WW], (int)s[15 * WW + 15]));
        sbase[a] = (unsigned char)min(m, NR - WR);
    }
    __syncthreads();

    // ---- delta-packed idx: sidxp[b*97 + k] = 2 angles (2k, 2k+1),
    //      each 14b: r0(5) | d1(3) | d2(3) | d3(3), walk 00->10->11->01 ----
    for (int i2 = tid; i2 < 64 * 90; i2 += TPB) {
        int bb = i2 / 90, k = i2 - bb * 90;
        int ggx = x0 + 2 * (bb & 7), ggy = y0 + 2 * (bb >> 3);
        unsigned wout = 0;
        #pragma unroll
        for (int h = 0; h < 2; h++) {
            int a = 2 * k + h;
            const unsigned char* s = g_idx + (size_t)a * PIX + ggy * WW + ggx;
            unsigned t = *(const unsigned short*)s;          // r00 | r10<<8
            unsigned u = *(const unsigned short*)(s + WW);   // r01 | r11<<8
            int r00 = t & 255, r10 = t >> 8;
            int r01 = u & 255, r11 = u >> 8;
            int r0 = r00 - (int)sbase[a];
            int d1 = r10 - r00;
            int d2 = r11 - r10;
            int d3 = r01 - r11;
            unsigned hh = (unsigned)r0 | ((unsigned)(d1 & 7) << 5)
                        | ((unsigned)(d2 & 7) << 8) | ((unsigned)(d3 & 7) << 11);
            wout |= hh << (16 * h);
        }
        sidxp[bb * 97 + k] = wout;
    }
    __syncthreads();

    // ---- staging: phase f -> iter i = f/15 (16 ch), angle block ph*12 ----
    auto stage = [&](int f) {
        int i = f / PPI, ph = f - i * PPI;
        int czb = cz0 + i * 16;
        int a0 = ph * PH;
        unsigned sd = (unsigned)__cvta_generic_to_shared(sbuf[f & 1]);
        #pragma unroll
        for (int it = 0; it < 4; it++) {
            int e = tid + it * TPB;
            if (e < PH * 4 * WR) {                 // 960 granules of 16B
                int al  = e / (4 * WR);
                int rem = e - al * (4 * WR);
                int jj  = rem / WR;
                int row = rem - jj * WR;
                int a = a0 + al;
                int r = (int)sbase[a] + row;
                cp16(sd + (e << 4),
                     g_T + ((size_t)a * NR + r) * NC + czb + jj * 4);
            }
        }
        asm volatile("cp.async.commit_group;\n" ::: "memory");
    };

    // ---- accumulators: 4 pixels x 4 ch (2 u64 each) ----
    unsigned long long a00_0 = 0, a00_1 = 0, a10_0 = 0, a10_1 = 0;
    unsigned long long a11_0 = 0, a11_1 = 0, a01_0 = 0, a01_1 = 0;

    const unsigned* myidx = sidxp + b * 97;

#define STEP0(A0, A1, W, B, SA)                                               \
    asm volatile("{\n\t"                                                      \
        ".reg .u32 rr;\n\t"                                                   \
        "bfe.u32 rr, %5, %6, 5;\n\t"                                          \
        "mad.lo.u32 %4, rr, 16, %7;\n\t"                                      \
        "ld.shared.v2.u64 {%2, %3}, [%4];\n\t"                                \
        "add.rn.f32x2 %0, %0, %2;\n\t"                                        \
        "add.rn.f32x2 %1, %1, %3;\n\t"                                        \
        "}"                                                                   \
        : "+l"(A0), "+l"(A1), "+l"(v0), "+l"(v1), "+r"(ad)                    \
        : "r"(W), "n"(B), "r"(SA))

#define STEPD(A0, A1, W, B)                                                   \
    asm volatile("{\n\t"                                                      \
        ".reg .pred p;\n\t"                                                   \
        ".reg .s32 d;\n\t"                                                    \
        "bfe.s32 d, %5, %6, 3;\n\t"                                           \
        "setp.ne.s32 p, d, 0;\n\t"                                            \
        "mad.lo.s32 %4, d, 16, %4;\n\t"                                       \
        "@p ld.shared.v2.u64 {%2, %3}, [%4];\n\t"                             \
        "add.rn.f32x2 %0, %0, %2;\n\t"                                        \
        "add.rn.f32x2 %1, %1, %3;\n\t"                                        \
        "}"                                                                   \
        : "+l"(A0), "+l"(A1), "+l"(v0), "+l"(v1), "+r"(ad)                    \
        : "r"(W), "n"(B))

#define ANGLE(W, B, SA) do {                                                  \
        STEP0(a00_0, a00_1, W, B, SA);                                        \
        STEPD(a10_0, a10_1, W, (B)+5);                                        \
        STEPD(a11_0, a11_1, W, (B)+8);                                        \
        STEPD(a01_0, a01_1, W, (B)+11);                                       \
    } while (0)

    stage(0);

    #pragma unroll 1
    for (int f = 0; f < NF; f++) {
        asm volatile("cp.async.wait_group 0;\n" ::: "memory");
        __syncthreads();
        if (f + 1 < NF) stage(f + 1);

        int i  = f / PPI;
        int ph = f - i * PPI;
        const unsigned* ip = myidx + ph * (PH / 2);
        unsigned sbj = (unsigned)__cvta_generic_to_shared(sbuf[f & 1])
                       + (unsigned)(j * (WR * 16));

        unsigned long long v0 = 0, v1 = 0;
        unsigned ad = 0;

        #pragma unroll
        for (int q = 0; q < PH / 2; q++) {
            unsigned wv = ip[q];
            unsigned sA = sbj + (unsigned)(2 * q) * (4 * WR * 16);
            ANGLE(wv, 0, sA);
            ANGLE(wv, 16, sA + (4 * WR * 16));
        }

        if (ph == PPI - 1) {
            int czb = cz0 + i * 16 + j * 4;
            float* ob = out + (size_t)czb * PIX + gy * WW + gx;
            #pragma unroll
            for (int cc = 0; cc < 4; cc++) {
                unsigned long long s00 = (cc < 2) ? a00_0 : a00_1;
                unsigned long long s10 = (cc < 2) ? a10_0 : a10_1;
                unsigned long long s01 = (cc < 2) ? a01_0 : a01_1;
                unsigned long long s11 = (cc < 2) ? a11_0 : a11_1;
                int hi = cc & 1;
                float2 t0, t1;
                t0.x = __uint_as_float(hi ? (unsigned)(s00 >> 32) : (unsigned)s00);
                t0.y = __uint_as_float(hi ? (unsigned)(s10 >> 32) : (unsigned)s10);
                t1.x = __uint_as_float(hi ? (unsigned)(s01 >> 32) : (unsigned)s01);
                t1.y = __uint_as_float(hi ? (unsigned)(s11 >> 32) : (unsigned)s11);
                float* oc = ob + (size_t)cc * PIX;
                *(float2*)oc = t0;
                *(float2*)(oc + WW) = t1;
            }
            a00_0 = a00_1 = a10_0 = a10_1 = 0;
            a11_0 = a11_1 = a01_0 = a01_1 = 0;
        }
    }
#undef ANGLE
#undef STEPD
#undef STEP0
}

// ---------------------------------------------------------------------------
extern "C" void kernel_launch(void* const* d_in, const int* in_sizes, int n_in,
                              void* d_out, int out_size)
{
    const float* hough = (const float*)d_in[0];
    float* out = (float*)d_out;

    tab_kernel<<<1, 256>>>();
    build_idx_kernel<<<dim3(PIX / 256, NA), 256>>>();
    transpose_kernel<<<dim3((AR + 31) / 32, NC / 32), dim3(32, 8)>>>(hough);
    iht_main_kernel<<<dim3(10, 10, 8), TPB>>>(out);
}

// round 7
// speedup vs baseline: 1.0003x; 1.0003x over previous
#include <cuda_runtime.h>
#include <cstdint>
#include <cstddef>

// Problem constants
#define NB   8
#define CB   128
#define NC   1024          // NB*CB
#define HH   160
#define WW   160
#define NA   180
#define NR   180
#define AR   (NA*NR)       // 32400
#define PIX  (HH*WW)       // 25600
#define WR   20            // staged rho-window rows (true span <= 18)
#define PH   12            // angles per staging phase
#define PPI  15            // phases per chunk-iter (NA/PH)
#define ITERS 8            // channel iters per CTA (128 ch / 16)
#define NF   (ITERS*PPI)   // 120 total phases
#define TPB  256

// Scratch in __device__ globals (no allocation allowed)
__device__ float         g_T[(size_t)AR * NC];       // transposed: T[a][r][nc]
__device__ unsigned char g_idx[(size_t)NA * PIX];    // r index table [a][y][x]
__device__ double        g_tab[2 * NA];              // cos/irho, sin/irho

// ---------------------------------------------------------------------------
// Kernel 0: trig table (fp64, once)
// ---------------------------------------------------------------------------
__global__ void tab_kernel()
{
    int a = threadIdx.x;
    if (a < NA) {
        const double PI = 3.14159265358979323846;
        double th = (double)a * (PI / 180.0);
        double irho = 227.0 / 180.0;   // (int(sqrt(160^2+160^2))+1)/180
        g_tab[a]      = cos(th) / irho;
        g_tab[NA + a] = sin(th) / irho;
    }
}

// ---------------------------------------------------------------------------
// Kernel 1: rho-index table (fp64 FMA-class ops only; matches numpy exactly)
// ---------------------------------------------------------------------------
__global__ void build_idx_kernel()
{
    const int a = blockIdx.y;
    double tc = g_tab[a], ts = g_tab[NA + a];
    int p = blockIdx.x * 256 + threadIdx.x;
    int y = p / WW, x = p - y * WW;
    double v = __dadd_rn(__dmul_rn((double)(x - 80), tc),
                         __dmul_rn((double)(y - 80), ts));
    int r = (int)rint(v) + 90;
    r = min(NR - 1, max(0, r));
    g_idx[(size_t)a * PIX + p] = (unsigned char)r;
}

// ---------------------------------------------------------------------------
// Kernel 2: transpose In[NC][AR] -> T[AR][NC]
// ---------------------------------------------------------------------------
__global__ void transpose_kernel(const float* __restrict__ in)
{
    __shared__ float tile[32][33];
    int ar0 = blockIdx.x * 32;
    int nc0 = blockIdx.y * 32;
    int tx = threadIdx.x;
    int ty = threadIdx.y;
    #pragma unroll
    for (int i = ty; i < 32; i += 8) {
        int ar = ar0 + tx;
        if (ar < AR) tile[i][tx] = in[(size_t)(nc0 + i) * AR + ar];
    }
    __syncthreads();
    #pragma unroll
    for (int i = ty; i < 32; i += 8) {
        int ar = ar0 + i;
        if (ar < AR) g_T[(size_t)ar * NC + nc0 + tx] = tile[tx][i];
    }
}

// ---------------------------------------------------------------------------
// Kernel 3: main inverse-Hough.
//   CTA = 16x16 pixel tile x 128 ch, 256 thr.
//   Thread = 2x2 pixel block (b = tid&63) x 4-ch slot (j = tid>>6).
//   Walk 00->10->11->01 per angle with delta-packed idx (r0:5b + 3x3b
//   signed deltas, 2 angles per u32). Reload (predicated, branch-free)
//   only when delta != 0 => ~2.5 LDS.128 per 4 pixels instead of 4.
//   Values staged per phase (12 angles x 20 rows x 16 ch) via cp.async,
//   double-buffered.
// ---------------------------------------------------------------------------
__device__ __forceinline__ void cp16(unsigned smem_addr, const void* gptr)
{
    asm volatile("cp.async.cg.shared.global [%0], [%1], 16;\n"
                 :: "r"(smem_addr), "l"(gptr));
}

__global__ void __launch_bounds__(TPB, 3) iht_main_kernel(float* __restrict__ out)
{
    __shared__ __align__(16) char sbuf[2][PH * 4 * WR * 16];  // 2 x 15360 B
    __shared__ unsigned sidxp[64 * 97];                       // 24832 B
    __shared__ unsigned char sbase[192];

    const int tid = threadIdx.x;
    const int x0 = blockIdx.x * 16;
    const int y0 = blockIdx.y * 16;
    const int cz0 = blockIdx.z * 128;
    const int b  = tid & 63;
    const int j  = tid >> 6;
    const int bx = b & 7, by = b >> 3;
    const int gx = x0 + 2 * bx, gy = y0 + 2 * by;

    // ---- per-angle window base (min over tile corners; affine => corners) ----
    for (int a = tid; a < NA; a += TPB) {
        const unsigned char* s = g_idx + (size_t)a * PIX + y0 * WW + x0;
        int m = min(min((int)s[0], (int)s[15]),
                    min((int)s[15 * WW], (int)s[15 * WW + 15]));
        sbase[a] = (unsigned char)min(m, NR - WR);
    }
    __syncthreads();

    // ---- delta-packed idx: sidxp[b*97 + k] = 2 angles (2k, 2k+1),
    //      each 14b: r0(5) | d1(3) | d2(3) | d3(3), walk 00->10->11->01 ----
    for (int i2 = tid; i2 < 64 * 90; i2 += TPB) {
        int bb = i2 / 90, k = i2 - bb * 90;
        int ggx = x0 + 2 * (bb & 7), ggy = y0 + 2 * (bb >> 3);
        unsigned wout = 0;
        #pragma unroll
        for (int h = 0; h < 2; h++) {
            int a = 2 * k + h;
            const unsigned char* s = g_idx + (size_t)a * PIX + ggy * WW + ggx;
            unsigned t = *(const unsigned short*)s;          // r00 | r10<<8
            unsigned u = *(const unsigned short*)(s + WW);   // r01 | r11<<8
            int r00 = t & 255, r10 = t >> 8;
            int r01 = u & 255, r11 = u >> 8;
            int r0 = r00 - (int)sbase[a];
            int d1 = r10 - r00;
            int d2 = r11 - r10;
            int d3 = r01 - r11;
            unsigned hh = (unsigned)r0 | ((unsigned)(d1 & 7) << 5)
                        | ((unsigned)(d2 & 7) << 8) | ((unsigned)(d3 & 7) << 11);
            wout |= hh << (16 * h);
        }
        sidxp[bb * 97 + k] = wout;
    }
    __syncthreads();

    // ---- staging: phase f -> iter i = f/15 (16 ch), angle block ph*12 ----
    auto stage = [&](int f) {
        int i = f / PPI, ph = f - i * PPI;
        int czb = cz0 + i * 16;
        int a0 = ph * PH;
        unsigned sd = (unsigned)__cvta_generic_to_shared(sbuf[f & 1]);
        #pragma unroll
        for (int it = 0; it < 4; it++) {
            int e = tid + it * TPB;
            if (e < PH * 4 * WR) {                 // 960 granules of 16B
                int al  = e / (4 * WR);
                int rem = e - al * (4 * WR);
                int jj  = rem / WR;
                int row = rem - jj * WR;
                int a = a0 + al;
                int r = (int)sbase[a] + row;
                cp16(sd + (e << 4),
                     g_T + ((size_t)a * NR + r) * NC + czb + jj * 4);
            }
        }
        asm volatile("cp.async.commit_group;\n" ::: "memory");
    };

    // ---- accumulators: 4 pixels x 4 ch (2 u64 each) ----
    unsigned long long a00_0 = 0, a00_1 = 0, a10_0 = 0, a10_1 = 0;
    unsigned long long a11_0 = 0, a11_1 = 0, a01_0 = 0, a01_1 = 0;

    const unsigned* myidx = sidxp + b * 97;

#define STEP0(A0, A1, W, B, SA)                                               \
    asm volatile("{\n\t"                                                      \
        ".reg .u32 rr;\n\t"                                                   \
        "bfe.u32 rr, %5, %6, 5;\n\t"                                          \
        "mad.lo.u32 %4, rr, 16, %7;\n\t"                                      \
        "ld.shared.v2.u64 {%2, %3}, [%4];\n\t"                                \
        "add.rn.f32x2 %0, %0, %2;\n\t"                                        \
        "add.rn.f32x2 %1, %1, %3;\n\t"                                        \
        "}"                                                                   \
        : "+l"(A0), "+l"(A1), "+l"(v0), "+l"(v1), "+r"(ad)                    \
        : "r"(W), "n"(B), "r"(SA))

#define STEPD(A0, A1, W, B)                                                   \
    asm volatile("{\n\t"                                                      \
        ".reg .pred p;\n\t"                                                   \
        ".reg .s32 d;\n\t"                                                    \
        "bfe.s32 d, %5, %6, 3;\n\t"                                           \
        "setp.ne.s32 p, d, 0;\n\t"                                            \
        "mad.lo.s32 %4, d, 16, %4;\n\t"                                       \
        "@p ld.shared.v2.u64 {%2, %3}, [%4];\n\t"                             \
        "add.rn.f32x2 %0, %0, %2;\n\t"                                        \
        "add.rn.f32x2 %1, %1, %3;\n\t"                                        \
        "}"                                                                   \
        : "+l"(A0), "+l"(A1), "+l"(v0), "+l"(v1), "+r"(ad)                    \
        : "r"(W), "n"(B))

#define ANGLE(W, B, SA) do {                                                  \
        STEP0(a00_0, a00_1, W, B, SA);                                        \
        STEPD(a10_0, a10_1, W, (B)+5);                                        \
        STEPD(a11_0, a11_1, W, (B)+8);                                        \
        STEPD(a01_0, a01_1, W, (B)+11);                                       \
    } while (0)

    stage(0);

    #pragma unroll 1
    for (int f = 0; f < NF; f++) {
        asm volatile("cp.async.wait_group 0;\n" ::: "memory");
        __syncthreads();
        if (f + 1 < NF) stage(f + 1);

        int i  = f / PPI;
        int ph = f - i * PPI;
        const unsigned* ip = myidx + ph * (PH / 2);
        unsigned sbj = (unsigned)__cvta_generic_to_shared(sbuf[f & 1])
                       + (unsigned)(j * (WR * 16));

        unsigned long long v0 = 0, v1 = 0;
        unsigned ad = 0;

        #pragma unroll
        for (int q = 0; q < PH / 2; q++) {
            unsigned wv = ip[q];
            unsigned sA = sbj + (unsigned)(2 * q) * (4 * WR * 16);
            ANGLE(wv, 0, sA);
            ANGLE(wv, 16, sA + (4 * WR * 16));
        }

        if (ph == PPI - 1) {
            int czb = cz0 + i * 16 + j * 4;
            float* ob = out + (size_t)czb * PIX + gy * WW + gx;
            #pragma unroll
            for (int cc = 0; cc < 4; cc++) {
                unsigned long long s00 = (cc < 2) ? a00_0 : a00_1;
                unsigned long long s10 = (cc < 2) ? a10_0 : a10_1;
                unsigned long long s01 = (cc < 2) ? a01_0 : a01_1;
                unsigned long long s11 = (cc < 2) ? a11_0 : a11_1;
                int hi = cc & 1;
                float2 t0, t1;
                t0.x = __uint_as_float(hi ? (unsigned)(s00 >> 32) : (unsigned)s00);
                t0.y = __uint_as_float(hi ? (unsigned)(s10 >> 32) : (unsigned)s10);
                t1.x = __uint_as_float(hi ? (unsigned)(s01 >> 32) : (unsigned)s01);
                t1.y = __uint_as_float(hi ? (unsigned)(s11 >> 32) : (unsigned)s11);
                float* oc = ob + (size_t)cc * PIX;
                *(float2*)oc = t0;
                *(float2*)(oc + WW) = t1;
            }
            a00_0 = a00_1 = a10_0 = a10_1 = 0;
            a11_0 = a11_1 = a01_0 = a01_1 = 0;
        }
    }
#undef ANGLE
#undef STEPD
#undef STEP0
}

// ---------------------------------------------------------------------------
extern "C" void kernel_launch(void* const* d_in, const int* in_sizes, int n_in,
                              void* d_out, int out_size)
{
    const float* hough = (const float*)d_in[0];
    float* out = (float*)d_out;

    tab_kernel<<<1, 256>>>();
    build_idx_kernel<<<dim3(PIX / 256, NA), 256>>>();
    transpose_kernel<<<dim3((AR + 31) / 32, NC / 32), dim3(32, 8)>>>(hough);
    iht_main_kernel<<<dim3(10, 10, 8), TPB>>>(out);
}

// round 8
// speedup vs baseline: 1.3913x; 1.3908x over previous
#include <cuda_runtime.h>
#include <cstdint>
#include <cstddef>

// Problem constants
#define NB   8
#define CB   128
#define NC   1024          // NB*CB
#define HH   160
#define WW   160
#define NA   180
#define NR   180
#define AR   (NA*NR)       // 32400
#define PIX  (HH*WW)       // 25600
#define WR   20            // staged rho-window rows (true span <= 18 for 16x16)
#define PH   3             // angles per staging phase
#define NPHASE (NA/PH)     // 60
#define TPB  1024
#define BUFB (PH*WR*512)   // 30720 B per buffer

// Scratch in __device__ globals (no allocation allowed)
__device__ float         g_T[(size_t)AR * NC];       // transposed: T[a][r][nc]
__device__ unsigned char g_idx[(size_t)NA * PIX];    // r index table [a][y][x]
__device__ double        g_tab[2 * NA];              // cos/irho, sin/irho

// ---------------------------------------------------------------------------
// Kernel 0: trig table (fp64, once)
// ---------------------------------------------------------------------------
__global__ void tab_kernel()
{
    int a = threadIdx.x;
    if (a < NA) {
        const double PI = 3.14159265358979323846;
        double th = (double)a * (PI / 180.0);
        double irho = 227.0 / 180.0;   // (int(sqrt(160^2+160^2))+1)/180
        g_tab[a]      = cos(th) / irho;
        g_tab[NA + a] = sin(th) / irho;
    }
}

// ---------------------------------------------------------------------------
// Kernel 1: rho-index table (fp64 FMA-class ops only; matches numpy exactly)
// ---------------------------------------------------------------------------
__global__ void build_idx_kernel()
{
    const int a = blockIdx.y;
    double tc = g_tab[a], ts = g_tab[NA + a];
    int p = blockIdx.x * 256 + threadIdx.x;
    int y = p / WW, x = p - y * WW;
    double v = __dadd_rn(__dmul_rn((double)(x - 80), tc),
                         __dmul_rn((double)(y - 80), ts));
    int r = (int)rint(v) + 90;
    r = min(NR - 1, max(0, r));
    g_idx[(size_t)a * PIX + p] = (unsigned char)r;
}

// ---------------------------------------------------------------------------
// Kernel 2: transpose In[NC][AR] -> T[AR][NC]
// ---------------------------------------------------------------------------
__global__ void transpose_kernel(const float* __restrict__ in)
{
    __shared__ float tile[32][33];
    int ar0 = blockIdx.x * 32;
    int nc0 = blockIdx.y * 32;
    int tx = threadIdx.x;
    int ty = threadIdx.y;
    #pragma unroll
    for (int i = ty; i < 32; i += 8) {
        int ar = ar0 + tx;
        if (ar < AR) tile[i][tx] = in[(size_t)(nc0 + i) * AR + ar];
    }
    __syncthreads();
    #pragma unroll
    for (int i = ty; i < 32; i += 8) {
        int ar = ar0 + i;
        if (ar < AR) g_T[(size_t)ar * NC + nc0 + tx] = tile[tx][i];
    }
}

// ---------------------------------------------------------------------------
// Kernel 3: main inverse-Hough.
//   CTA = 16x16 pixel tile x 128 ch, 1024 thr = 32 warps.
//   Warp = one 4x2 pixel block; lane = 4 consecutive channels (128 ch/warp).
//   Value loads: whole warp reads ONE staged 512B row -> 4 dense wavefronts,
//   ZERO bank conflicts. Thread walks its 8 pixels serpentine per angle;
//   reload (uniform-predicated) only on r-change: ~2.9 loads / 8 px / angle.
//   Index: packed 26-bit per (block, angle): r0(5b) + 7 x 3b signed deltas,
//   walk order chosen per angle (x-fast for 45<=a<135, else y-fast).
//   Values cp.async-staged (3 angles x 20 rows x 512B), double-buffered.
// ---------------------------------------------------------------------------
__device__ __forceinline__ void cp16(unsigned smem_addr, const void* gptr)
{
    asm volatile("cp.async.cg.shared.global [%0], [%1], 16;\n"
                 :: "r"(smem_addr), "l"(gptr));
}

__global__ void __launch_bounds__(TPB, 1) iht_main_kernel(float* __restrict__ out)
{
    __shared__ __align__(16) char sbuf[2][BUFB];     // 61440 B
    __shared__ unsigned sw[32 * NA];                 // 23040 B
    __shared__ unsigned char sbase[192];

    const int tid = threadIdx.x;
    const int x0 = blockIdx.x * 16;
    const int y0 = blockIdx.y * 16;
    const int cz0 = blockIdx.z * 128;
    const int lane = tid & 31;
    const int w = tid >> 5;                          // warp = pixel block id

    // ---- per-angle window base (min over tile corners; affine => corners) ----
    if (tid < NA) {
        const unsigned char* s = g_idx + (size_t)tid * PIX + y0 * WW + x0;
        int m = min(min((int)s[0], (int)s[15]),
                    min((int)s[15 * WW], (int)s[15 * WW + 15]));
        sbase[tid] = (unsigned char)min(m, NR - WR);
    }
    __syncthreads();

    // ---- staging ----
    auto stage = [&](int f) {
        int a0 = f * PH;
        unsigned sd = (unsigned)__cvta_generic_to_shared(sbuf[f & 1]);
        #pragma unroll
        for (int it = 0; it < 2; it++) {
            int e = tid + it * TPB;
            if (e < PH * WR * 32) {                  // 1920 granules of 16B
                int s   = e / (WR * 32);
                int rem = e - s * (WR * 32);
                int row = rem >> 5;
                int c   = rem & 31;
                int a = a0 + s;
                int r = (int)sbase[a] + row;
                cp16(sd + (e << 4),
                     g_T + ((size_t)a * NR + r) * NC + cz0 + c * 4);
            }
        }
        asm volatile("cp.async.commit_group;\n" ::: "memory");
    };

    stage(0);

    // ---- build packed walk records: sw[blk*180 + a] ----
    for (int i = tid; i < 32 * NA; i += TPB) {
        int a = i >> 5, blk = i & 31;
        int ggx = x0 + 4 * (blk & 3);
        int ggy = y0 + 2 * (blk >> 2);
        const unsigned char* s = g_idx + (size_t)a * PIX + ggy * WW + ggx;
        unsigned t0 = *(const unsigned*)s;           // row0: px (0..3, y=0)
        unsigned t1 = *(const unsigned*)(s + WW);    // row1: px (0..3, y=1)
        int A0 = t0 & 255, A1 = (t0 >> 8) & 255, A2 = (t0 >> 16) & 255, A3 = t0 >> 24;
        int B0 = t1 & 255, B1 = (t1 >> 8) & 255, B2 = (t1 >> 16) & 255, B3 = t1 >> 24;
        int q1, q2, q3, q4, q5, q6, q7;
        if (a >= 45 && a < 135) {   // x-fast: (0,0)(1,0)(2,0)(3,0)(3,1)(2,1)(1,1)(0,1)
            q1 = A1; q2 = A2; q3 = A3; q4 = B3; q5 = B2; q6 = B1; q7 = B0;
        } else {                    // y-fast: (0,0)(0,1)(1,1)(1,0)(2,0)(2,1)(3,1)(3,0)
            q1 = B0; q2 = B1; q3 = A1; q4 = A2; q5 = B2; q6 = B3; q7 = A3;
        }
        unsigned wv = (unsigned)(A0 - (int)sbase[a]);
        wv |= ((unsigned)((q1 - A0) & 7)) << 5;
        wv |= ((unsigned)((q2 - q1) & 7)) << 8;
        wv |= ((unsigned)((q3 - q2) & 7)) << 11;
        wv |= ((unsigned)((q4 - q3) & 7)) << 14;
        wv |= ((unsigned)((q5 - q4) & 7)) << 17;
        wv |= ((unsigned)((q6 - q5) & 7)) << 20;
        wv |= ((unsigned)((q7 - q6) & 7)) << 23;
        sw[blk * NA + a] = wv;
    }
    __syncthreads();

    // ---- accumulators: 8 px x 4 ch = 16 u64 (px index = x + 4y) ----
    unsigned long long acc[16];
    #pragma unroll
    for (int i = 0; i < 16; i++) acc[i] = 0ull;

#define STEP0(PX)                                                             \
    asm volatile("{\n\t"                                                      \
        ".reg .u32 rr;\n\t"                                                   \
        "bfe.u32 rr, %5, 0, 5;\n\t"                                           \
        "mad.lo.u32 %4, rr, 512, %6;\n\t"                                     \
        "ld.shared.v2.u64 {%2, %3}, [%4];\n\t"                                \
        "add.rn.f32x2 %0, %0, %2;\n\t"                                        \
        "add.rn.f32x2 %1, %1, %3;\n\t"                                        \
        "}"                                                                   \
        : "+l"(acc[2*(PX)]), "+l"(acc[2*(PX)+1]),                             \
          "+l"(v0), "+l"(v1), "=r"(ad)                                        \
        : "r"(wv), "r"(sA))

#define STEPD(PX, K)                                                          \
    asm volatile("{\n\t"                                                      \
        ".reg .pred p;\n\t .reg .s32 d;\n\t"                                  \
        "bfe.s32 d, %5, %6, 3;\n\t"                                           \
        "setp.ne.s32 p, d, 0;\n\t"                                            \
        "mad.lo.s32 %4, d, 512, %4;\n\t"                                      \
        "@p ld.shared.v2.u64 {%2, %3}, [%4];\n\t"                             \
        "add.rn.f32x2 %0, %0, %2;\n\t"                                        \
        "add.rn.f32x2 %1, %1, %3;\n\t"                                        \
        "}"                                                                   \
        : "+l"(acc[2*(PX)]), "+l"(acc[2*(PX)+1]),                             \
          "+l"(v0), "+l"(v1), "+r"(ad)                                        \
        : "r"(wv), "n"(5 + 3*((K)-1)))

    const unsigned swb = w * NA;
    unsigned bufa0 = (unsigned)__cvta_generic_to_shared(sbuf[0]) + (lane << 4);

    #pragma unroll 1
    for (int f = 0; f < NPHASE; f++) {
        asm volatile("cp.async.wait_group 0;\n" ::: "memory");
        __syncthreads();
        if (f + 1 < NPHASE) stage(f + 1);

        unsigned bufa = bufa0 + (unsigned)((f & 1) * BUFB);
        #pragma unroll
        for (int s = 0; s < PH; s++) {
            int a = f * PH + s;
            unsigned wv = sw[swb + a];
            unsigned sA = bufa + (unsigned)(s * (WR * 512));
            unsigned long long v0 = 0, v1 = 0;
            unsigned ad;
            if (a >= 45 && a < 135) {   // x-fast: acc order 0,1,2,3,7,6,5,4
                STEP0(0);    STEPD(1,1); STEPD(2,2); STEPD(3,3);
                STEPD(7,4);  STEPD(6,5); STEPD(5,6); STEPD(4,7);
            } else {                    // y-fast: acc order 0,4,5,1,2,6,7,3
                STEP0(0);    STEPD(4,1); STEPD(5,2); STEPD(1,3);
                STEPD(2,4);  STEPD(6,5); STEPD(7,6); STEPD(3,7);
            }
        }
    }
#undef STEPD
#undef STEP0

    // ---- epilogue: per ch, per row: float4 over the 4-wide block ----
    const int gx = x0 + 4 * (w & 3);
    const int gy = y0 + 2 * (w >> 2);
    const int c0 = cz0 + lane * 4;
    #pragma unroll
    for (int y = 0; y < 2; y++) {
        #pragma unroll
        for (int cc = 0; cc < 4; cc++) {
            int half = cc & 1, sel = cc >> 1;
            float4 o;
            unsigned long long s0 = acc[(0 + 4*y)*2 + sel];
            unsigned long long s1 = acc[(1 + 4*y)*2 + sel];
            unsigned long long s2 = acc[(2 + 4*y)*2 + sel];
            unsigned long long s3 = acc[(3 + 4*y)*2 + sel];
            o.x = __uint_as_float(half ? (unsigned)(s0 >> 32) : (unsigned)s0);
            o.y = __uint_as_float(half ? (unsigned)(s1 >> 32) : (unsigned)s1);
            o.z = __uint_as_float(half ? (unsigned)(s2 >> 32) : (unsigned)s2);
            o.w = __uint_as_float(half ? (unsigned)(s3 >> 32) : (unsigned)s3);
            *(float4*)(out + (size_t)(c0 + cc) * PIX + (gy + y) * WW + gx) = o;
        }
    }
}

// ---------------------------------------------------------------------------
extern "C" void kernel_launch(void* const* d_in, const int* in_sizes, int n_in,
                              void* d_out, int out_size)
{
    const float* hough = (const float*)d_in[0];
    float* out = (float*)d_out;

    tab_kernel<<<1, 256>>>();
    build_idx_kernel<<<dim3(PIX / 256, NA), 256>>>();
    transpose_kernel<<<dim3((AR + 31) / 32, NC / 32), dim3(32, 8)>>>(hough);
    iht_main_kernel<<<dim3(10, 10, 8), TPB>>>(out);
}

// round 9
// speedup vs baseline: 1.7533x; 1.2602x over previous
#include <cuda_runtime.h>
#include <cstdint>
#include <cstddef>

// Problem constants
#define NB   8
#define CB   128
#define NC   1024          // NB*CB
#define HH   160
#define WW   160
#define NA   180
#define NR   180
#define AR   (NA*NR)       // 32400
#define PIX  (HH*WW)       // 25600
#define WR   16            // staged rho-window rows (16x8 tile span <= 15)
#define PH   3             // angles per staging phase
#define NPHASE (NA/PH)     // 60
#define TPB  512
#define BUFB (PH*WR*512)   // 24576 B per buffer

// Scratch in __device__ globals (no allocation allowed)
__device__ float         g_T[(size_t)AR * NC];       // transposed: T[a][r][nc]
__device__ unsigned char g_idx[(size_t)NA * PIX];    // r index table [a][y][x]
__device__ double        g_tab[2 * NA];              // cos/irho, sin/irho

// sorted walk orders (8 px of a 4x2 block, px = x + 4y), packed 3b per slot
__device__ const unsigned c_ord[8] = {
    0u|(4u<<3)|(1u<<6)|(5u<<9)|(2u<<12)|(6u<<15)|(3u<<18)|(7u<<21),  // [0,45)
    0u|(1u<<3)|(4u<<6)|(2u<<9)|(5u<<12)|(3u<<15)|(6u<<18)|(7u<<21),  // [45,63)
    0u|(1u<<3)|(2u<<6)|(4u<<9)|(3u<<12)|(5u<<15)|(6u<<18)|(7u<<21),  // [63,72)
    0u|(1u<<3)|(2u<<6)|(3u<<9)|(4u<<12)|(5u<<15)|(6u<<18)|(7u<<21),  // [72,90)
    3u|(2u<<3)|(1u<<6)|(0u<<9)|(7u<<12)|(6u<<15)|(5u<<18)|(4u<<21),  // [90,108)
    3u|(2u<<3)|(1u<<6)|(7u<<9)|(0u<<12)|(6u<<15)|(5u<<18)|(4u<<21),  // [108,117)
    3u|(2u<<3)|(7u<<6)|(1u<<9)|(6u<<12)|(0u<<15)|(5u<<18)|(4u<<21),  // [117,135)
    3u|(7u<<3)|(2u<<6)|(6u<<9)|(1u<<12)|(5u<<15)|(0u<<18)|(4u<<21)   // [135,180)
};

// ---------------------------------------------------------------------------
// Kernel 0: trig table (fp64, once)
// ---------------------------------------------------------------------------
__global__ void tab_kernel()
{
    int a = threadIdx.x;
    if (a < NA) {
        const double PI = 3.14159265358979323846;
        double th = (double)a * (PI / 180.0);
        double irho = 227.0 / 180.0;   // (int(sqrt(160^2+160^2))+1)/180
        g_tab[a]      = cos(th) / irho;
        g_tab[NA + a] = sin(th) / irho;
    }
}

// ---------------------------------------------------------------------------
// Kernel 1: rho-index table (fp64 FMA-class ops only; matches numpy exactly)
// ---------------------------------------------------------------------------
__global__ void build_idx_kernel()
{
    const int a = blockIdx.y;
    double tc = g_tab[a], ts = g_tab[NA + a];
    int p = blockIdx.x * 256 + threadIdx.x;
    int y = p / WW, x = p - y * WW;
    double v = __dadd_rn(__dmul_rn((double)(x - 80), tc),
                         __dmul_rn((double)(y - 80), ts));
    int r = (int)rint(v) + 90;
    r = min(NR - 1, max(0, r));
    g_idx[(size_t)a * PIX + p] = (unsigned char)r;
}

// ---------------------------------------------------------------------------
// Kernel 2: transpose In[NC][AR] -> T[AR][NC]
// ---------------------------------------------------------------------------
__global__ void transpose_kernel(const float* __restrict__ in)
{
    __shared__ float tile[32][33];
    int ar0 = blockIdx.x * 32;
    int nc0 = blockIdx.y * 32;
    int tx = threadIdx.x;
    int ty = threadIdx.y;
    #pragma unroll
    for (int i = ty; i < 32; i += 8) {
        int ar = ar0 + tx;
        if (ar < AR) tile[i][tx] = in[(size_t)(nc0 + i) * AR + ar];
    }
    __syncthreads();
    #pragma unroll
    for (int i = ty; i < 32; i += 8) {
        int ar = ar0 + i;
        if (ar < AR) g_T[(size_t)ar * NC + nc0 + tx] = tile[tx][i];
    }
}

// ---------------------------------------------------------------------------
// Kernel 3: main inverse-Hough.
//   CTA = 16x8 pixel tile x 128 ch, 512 thr = 16 warps, 2 CTAs/SM.
//   Warp = one 4x2 pixel block; lane = 4 consecutive channels.
//   Per angle the thread walks its 8 px in the SORTED-by-rho order (8
//   compile-time order classes over theta); r is monotone -> loads =
//   range+1 (minimum), deltas in {0,1}. Reloads uniform-predicated.
//   Whole warp reads one staged 512B row -> 4 dense conflict-free wf.
//   Values cp.async-staged (3 angles x 16 rows x 512B), double-buffered.
// ---------------------------------------------------------------------------
__device__ __forceinline__ void cp16(unsigned smem_addr, const void* gptr)
{
    asm volatile("cp.async.cg.shared.global [%0], [%1], 16;\n"
                 :: "r"(smem_addr), "l"(gptr));
}

__global__ void __launch_bounds__(TPB, 2) iht_main_kernel(float* __restrict__ out)
{
    __shared__ __align__(16) char sbuf[2][BUFB];     // 49152 B
    __shared__ unsigned sw[16 * NA];                 // 11520 B
    __shared__ unsigned char sbase[192];

    const int tid = threadIdx.x;
    const int x0 = blockIdx.x * 16;
    const int y0 = blockIdx.y * 8;
    const int cz0 = blockIdx.z * 128;
    const int lane = tid & 31;
    const int w = tid >> 5;                          // warp = pixel block id

    // ---- per-angle window base (min over tile corners; affine => corners) ----
    if (tid < NA) {
        const unsigned char* s = g_idx + (size_t)tid * PIX + y0 * WW + x0;
        int m = min(min((int)s[0], (int)s[15]),
                    min((int)s[7 * WW], (int)s[7 * WW + 15]));
        sbase[tid] = (unsigned char)min(m, NR - WR);
    }
    __syncthreads();

    // ---- staging ----
    auto stage = [&](int f) {
        int a0 = f * PH;
        unsigned sd = (unsigned)__cvta_generic_to_shared(sbuf[f & 1]);
        #pragma unroll
        for (int it = 0; it < 3; it++) {
            int e = tid + it * TPB;                  // 1536 granules of 16B
            int s   = e >> 9;
            int rem = e & 511;
            int row = rem >> 5;
            int c   = rem & 31;
            int a = a0 + s;
            int r = (int)sbase[a] + row;
            cp16(sd + (e << 4),
                 g_T + ((size_t)a * NR + r) * NC + cz0 + c * 4);
        }
        asm volatile("cp.async.commit_group;\n" ::: "memory");
    };

    stage(0);

    // ---- build packed sorted-walk records: sw[blk*180 + a] ----
    for (int i = tid; i < 16 * NA; i += TPB) {
        int blk = i & 15, a = i >> 4;
        int cls = a < 45 ? 0 : a < 63 ? 1 : a < 72 ? 2 : a < 90 ? 3
                : a < 108 ? 4 : a < 117 ? 5 : a < 135 ? 6 : 7;
        unsigned ord = c_ord[cls];
        const unsigned char* s = g_idx + (size_t)a * PIX
                                 + (y0 + 2 * (blk >> 2)) * WW + x0 + 4 * (blk & 3);
        unsigned t0 = *(const unsigned*)s;           // y=0 row: px 0..3
        unsigned t1 = *(const unsigned*)(s + WW);    // y=1 row: px 4..7
        int p = ord & 7;
        int prev = (int)(((p < 4 ? t0 : t1) >> (8 * (p & 3))) & 255u);
        unsigned wv = (unsigned)(prev - (int)sbase[a]);
        #pragma unroll
        for (int k = 1; k < 8; k++) {
            p = (ord >> (3 * k)) & 7;
            int cur = (int)(((p < 4 ? t0 : t1) >> (8 * (p & 3))) & 255u);
            wv |= ((unsigned)((cur - prev) & 7)) << (5 + 3 * (k - 1));
            prev = cur;
        }
        sw[blk * NA + a] = wv;
    }
    __syncthreads();

    // ---- accumulators: 8 px x 4 ch = 16 u64 (px index = x + 4y) ----
    unsigned long long acc[16];
    #pragma unroll
    for (int i = 0; i < 16; i++) acc[i] = 0ull;

#define STEP0(PX)                                                             \
    asm volatile("{\n\t"                                                      \
        ".reg .u32 rr;\n\t"                                                   \
        "bfe.u32 rr, %5, 0, 5;\n\t"                                           \
        "mad.lo.u32 %4, rr, 512, %6;\n\t"                                     \
        "ld.shared.v2.u64 {%2, %3}, [%4];\n\t"                                \
        "add.rn.f32x2 %0, %0, %2;\n\t"                                        \
        "add.rn.f32x2 %1, %1, %3;\n\t"                                        \
        "}"                                                                   \
        : "+l"(acc[2*(PX)]), "+l"(acc[2*(PX)+1]),                             \
          "+l"(v0), "+l"(v1), "=r"(ad)                                        \
        : "r"(wv), "r"(sA))

#define STEPD(PX, K)                                                          \
    asm volatile("{\n\t"                                                      \
        ".reg .pred p;\n\t .reg .s32 d;\n\t"                                  \
        "bfe.s32 d, %5, %6, 3;\n\t"                                           \
        "setp.ne.s32 p, d, 0;\n\t"                                            \
        "mad.lo.s32 %4, d, 512, %4;\n\t"                                      \
        "@p ld.shared.v2.u64 {%2, %3}, [%4];\n\t"                             \
        "add.rn.f32x2 %0, %0, %2;\n\t"                                        \
        "add.rn.f32x2 %1, %1, %3;\n\t"                                        \
        "}"                                                                   \
        : "+l"(acc[2*(PX)]), "+l"(acc[2*(PX)+1]),                             \
          "+l"(v0), "+l"(v1), "+r"(ad)                                        \
        : "r"(wv), "n"(5 + 3*((K)-1)))

#define DOSEG(F0, F1, Q0,Q1,Q2,Q3,Q4,Q5,Q6,Q7)                                \
    for (int f = (F0); f < (F1); f++) {                                       \
        asm volatile("cp.async.wait_group 0;\n" ::: "memory");                \
        __syncthreads();                                                      \
        if (f + 1 < NPHASE) stage(f + 1);                                     \
        unsigned bufa = bufa0 + (unsigned)((f & 1) * BUFB);                   \
        _Pragma("unroll")                                                     \
        for (int s2 = 0; s2 < PH; s2++) {                                     \
            unsigned wv = sw[swb + f * PH + s2];                              \
            unsigned sA = bufa + (unsigned)(s2 * (WR * 512));                 \
            unsigned long long v0 = 0, v1 = 0;                                \
            unsigned ad;                                                      \
            STEP0(Q0);    STEPD(Q1,1); STEPD(Q2,2); STEPD(Q3,3);              \
            STEPD(Q4,4);  STEPD(Q5,5); STEPD(Q6,6); STEPD(Q7,7);              \
        }                                                                     \
    }

    const unsigned swb = w * NA;
    unsigned bufa0 = (unsigned)__cvta_generic_to_shared(sbuf[0]) + (lane << 4);

    DOSEG( 0, 15, 0,4,1,5,2,6,3,7);   // a 0-44
    DOSEG(15, 21, 0,1,4,2,5,3,6,7);   // a 45-62
    DOSEG(21, 24, 0,1,2,4,3,5,6,7);   // a 63-71
    DOSEG(24, 30, 0,1,2,3,4,5,6,7);   // a 72-89
    DOSEG(30, 36, 3,2,1,0,7,6,5,4);   // a 90-107
    DOSEG(36, 39, 3,2,1,7,0,6,5,4);   // a 108-116
    DOSEG(39, 45, 3,2,7,1,6,0,5,4);   // a 117-134
    DOSEG(45, 60, 3,7,2,6,1,5,0,4);   // a 135-179
#undef DOSEG
#undef STEPD
#undef STEP0

    // ---- epilogue: per ch, per row: float4 over the 4-wide block ----
    const int gx = x0 + 4 * (w & 3);
    const int gy = y0 + 2 * (w >> 2);
    const int c0 = cz0 + lane * 4;
    #pragma unroll
    for (int y = 0; y < 2; y++) {
        #pragma unroll
        for (int cc = 0; cc < 4; cc++) {
            int half = cc & 1, sel = cc >> 1;
            float4 o;
            unsigned long long s0 = acc[(0 + 4*y)*2 + sel];
            unsigned long long s1 = acc[(1 + 4*y)*2 + sel];
            unsigned long long s2 = acc[(2 + 4*y)*2 + sel];
            unsigned long long s3 = acc[(3 + 4*y)*2 + sel];
            o.x = __uint_as_float(half ? (unsigned)(s0 >> 32) : (unsigned)s0);
            o.y = __uint_as_float(half ? (unsigned)(s1 >> 32) : (unsigned)s1);
            o.z = __uint_as_float(half ? (unsigned)(s2 >> 32) : (unsigned)s2);
            o.w = __uint_as_float(half ? (unsigned)(s3 >> 32) : (unsigned)s3);
            *(float4*)(out + (size_t)(c0 + cc) * PIX + (gy + y) * WW + gx) = o;
        }
    }
}

// ---------------------------------------------------------------------------
extern "C" void kernel_launch(void* const* d_in, const int* in_sizes, int n_in,
                              void* d_out, int out_size)
{
    const float* hough = (const float*)d_in[0];
    float* out = (float*)d_out;

    tab_kernel<<<1, 256>>>();
    build_idx_kernel<<<dim3(PIX / 256, NA), 256>>>();
    transpose_kernel<<<dim3((AR + 31) / 32, NC / 32), dim3(32, 8)>>>(hough);
    iht_main_kernel<<<dim3(10, 20, 8), TPB>>>(out);
}